// round 1
// baseline (speedup 1.0000x reference)
#include <cuda_runtime.h>
#include <cstddef>

#define IMG_W 256
#define IMG_H 256
#define RPB   128              // output rows per block (strip height)
#define STEPS (RPB + 8)       // pipeline steps: rows r-4 .. r+R+3

// Fused: edge = depthwise_conv(x, K5) + depthwise_conv(x, K3)  ==  one 5x5 kernel
//        == 2.2*x - 0.19*box3(x) - 0.01*box5(x)   (separable box sums)
// then out = |maxpool5x5_stride1_pad2(edge)|  (separable max, -inf padding)

__global__ void __launch_bounds__(64)
fused_edge_pool(const float* __restrict__ x, float* __restrict__ out)
{
    // xs: input row staged with +2 halo of zeros (conv zero padding)
    // es: edge row staged with +2 halo of -inf (maxpool -inf padding)
    __shared__ float xs[264];
    __shared__ float es[264];

    const int t  = threadIdx.x;        // 64 threads
    const int c0 = t << 2;             // 4 columns per thread -> full width 256
    const int plane = blockIdx.x >> 1; // B*C = 512 planes
    const int S     = (blockIdx.x & 1) ? RPB : 0;

    const float* __restrict__ xp = x   + (size_t)plane * (IMG_H * IMG_W);
    float*       __restrict__ op = out + (size_t)plane * (IMG_H * IMG_W);

    const float NINF = __int_as_float(0xff800000);

    if (t < 2) { xs[t] = 0.f; xs[258 + t] = 0.f; es[t] = NINF; es[258 + t] = NINF; }

    // Register rings (depth 5, static mod-5 indices via unroll-by-5):
    //  h3r/h5r: horizontal 3-wide / 5-wide sums of recent input rows
    //  xr     : recent input rows (center tap)
    //  hmr    : horizontal 5-max of recent edge rows
    //  pre    : LDG prefetch ring (distance 5 rows hides DRAM latency)
    float4 h3r[5], h5r[5], xr[5], hmr[5], pre[5];
#pragma unroll
    for (int i = 0; i < 5; ++i) {
        h3r[i] = make_float4(0.f, 0.f, 0.f, 0.f);
        h5r[i] = make_float4(0.f, 0.f, 0.f, 0.f);
        xr[i]  = make_float4(0.f, 0.f, 0.f, 0.f);
        hmr[i] = make_float4(NINF, NINF, NINF, NINF);
        const int rin = S - 4 + i;
        pre[i] = (rin >= 0 && rin < IMG_H)
               ? *reinterpret_cast<const float4*>(xp + rin * IMG_W + c0)
               : make_float4(0.f, 0.f, 0.f, 0.f);
    }
    __syncthreads();

    const float4* xs4 = reinterpret_cast<const float4*>(xs);
    const float4* es4 = reinterpret_cast<const float4*>(es);

#pragma unroll 1
    for (int ss = 0; ss < STEPS; ss += 5) {
#pragma unroll
        for (int k = 0; k < 5; ++k) {
            const int s = ss + k;
            if (s >= STEPS) break;           // uniform across block
            const int rin = S - 4 + s;       // input row consumed this step

            float4 xv = pre[k];
            const int rp = rin + 5;          // prefetch for step s+5
            pre[k] = (rp < IMG_H && s + 5 < STEPS)
                   ? *reinterpret_cast<const float4*>(xp + rp * IMG_W + c0)
                   : make_float4(0.f, 0.f, 0.f, 0.f);

            // ---- stage 1: stash input row, horizontal box sums ----
            *reinterpret_cast<float2*>(&xs[2 + c0]) = make_float2(xv.x, xv.y);
            *reinterpret_cast<float2*>(&xs[4 + c0]) = make_float2(xv.z, xv.w);
            __syncthreads();

            const float4 a = xs4[t];         // xs[4t .. 4t+3]  = x[c0-2 .. c0+1]
            const float4 b = xs4[t + 1];     // xs[4t+4 .. 4t+7]= x[c0+2 .. c0+5]
            const float w0 = a.x, w1 = a.y, w2 = a.z, w3 = a.w;
            const float w4 = b.x, w5 = b.y, w6 = b.z, w7 = b.w;

            float4 h3, h5;
            h3.x = w1 + w2 + w3;  h3.y = w2 + w3 + w4;
            h3.z = w3 + w4 + w5;  h3.w = w4 + w5 + w6;
            h5.x = h3.x + w0 + w4;  h5.y = h3.y + w1 + w5;
            h5.z = h3.z + w2 + w6;  h5.w = h3.w + w3 + w7;
            h3r[k] = h3;  h5r[k] = h5;  xr[k] = xv;

            // ---- stage 2: edge row re = rin-2 (vertical box sums) ----
            const int i1 = (k + 2) % 5, i2 = (k + 3) % 5, i3 = (k + 4) % 5;
            const float4 xc = xr[i2];
            float4 e;
            e.x = 2.2f * xc.x - 0.19f * (h3r[i1].x + h3r[i2].x + h3r[i3].x)
                - 0.01f * ((h5r[0].x + h5r[1].x) + (h5r[2].x + h5r[3].x) + h5r[4].x);
            e.y = 2.2f * xc.y - 0.19f * (h3r[i1].y + h3r[i2].y + h3r[i3].y)
                - 0.01f * ((h5r[0].y + h5r[1].y) + (h5r[2].y + h5r[3].y) + h5r[4].y);
            e.z = 2.2f * xc.z - 0.19f * (h3r[i1].z + h3r[i2].z + h3r[i3].z)
                - 0.01f * ((h5r[0].z + h5r[1].z) + (h5r[2].z + h5r[3].z) + h5r[4].z);
            e.w = 2.2f * xc.w - 0.19f * (h3r[i1].w + h3r[i2].w + h3r[i3].w)
                - 0.01f * ((h5r[0].w + h5r[1].w) + (h5r[2].w + h5r[3].w) + h5r[4].w);

            *reinterpret_cast<float2*>(&es[2 + c0]) = make_float2(e.x, e.y);
            *reinterpret_cast<float2*>(&es[4 + c0]) = make_float2(e.z, e.w);
            __syncthreads();

            // ---- stage 2b: horizontal 5-max of edge row ----
            const float4 ea = es4[t];
            const float4 eb = es4[t + 1];
            const float q0 = ea.x, q1 = ea.y, q2 = ea.z, q3 = ea.w;
            const float q4 = eb.x, q5 = eb.y, q6 = eb.z, q7 = eb.w;

            const int re = rin - 2;
            float4 hm;
            if (re >= 0 && re < IMG_H) {
                hm.x = fmaxf(fmaxf(fmaxf(q0, q1), fmaxf(q2, q3)), q4);
                hm.y = fmaxf(fmaxf(fmaxf(q1, q2), fmaxf(q3, q4)), q5);
                hm.z = fmaxf(fmaxf(fmaxf(q2, q3), fmaxf(q4, q5)), q6);
                hm.w = fmaxf(fmaxf(fmaxf(q3, q4), fmaxf(q5, q6)), q7);
            } else {
                hm = make_float4(NINF, NINF, NINF, NINF);   // -inf pool padding
            }
            hmr[k] = hm;

            // ---- stage 3: vertical 5-max + abs, write output row r = rin-4 ----
            if (s >= 8) {
                const int r = rin - 4;
                float4 o;
                o.x = fabsf(fmaxf(fmaxf(fmaxf(hmr[0].x, hmr[1].x),
                                        fmaxf(hmr[2].x, hmr[3].x)), hmr[4].x));
                o.y = fabsf(fmaxf(fmaxf(fmaxf(hmr[0].y, hmr[1].y),
                                        fmaxf(hmr[2].y, hmr[3].y)), hmr[4].y));
                o.z = fabsf(fmaxf(fmaxf(fmaxf(hmr[0].z, hmr[1].z),
                                        fmaxf(hmr[2].z, hmr[3].z)), hmr[4].z));
                o.w = fabsf(fmaxf(fmaxf(fmaxf(hmr[0].w, hmr[1].w),
                                        fmaxf(hmr[2].w, hmr[3].w)), hmr[4].w));
                *reinterpret_cast<float4*>(op + r * IMG_W + c0) = o;
            }
        }
    }
}

extern "C" void kernel_launch(void* const* d_in, const int* in_sizes, int n_in,
                              void* d_out, int out_size)
{
    const float* x = (const float*)d_in[0];
    float* out = (float*)d_out;
    const int planes = in_sizes[0] / (IMG_H * IMG_W);   // 512
    const int blocks = planes * (IMG_H / RPB);          // 1024
    fused_edge_pool<<<blocks, 64>>>(x, out);
}